// round 16
// baseline (speedup 1.0000x reference)
#include <cuda_runtime.h>

#define EMAX 800000
#define NMAX 100000
#define SLOPE_ 0.1f
#define EPS_ 1e-5f

// ---------------- scratch (device globals; no allocation allowed) ----------------
__device__ float g_hA[(size_t)EMAX * 64];   // edge intermediate A
__device__ float g_hB[(size_t)EMAX * 64];   // edge intermediate B
__device__ float g_agg[(size_t)NMAX * 64];  // scatter-sum result
__device__ float g_h2A[(size_t)NMAX * 96];
__device__ float g_h2B[(size_t)NMAX * 96];
__device__ int   g_deg[NMAX];
__device__ float g_sum[6][96];
__device__ float g_sq[6][96];
__device__ float g_Wf[6][96 * 96];          // folded (scale*W) per stage
__device__ __align__(16) float g_cf[6][96]; // folded bias per stage

// ---------------- merged prologue stats: ea col-stats + deg count + x col-stats ----------------
__global__ void k_edgestats(const float* __restrict__ ea, const float* __restrict__ x,
                            const int* __restrict__ row, int E, int N) {
    int b = blockIdx.x;
    if (b < 768) {
        const float* src = (b < 512) ? ea : x;
        int rows = (b < 512) ? E : N;
        int stage = (b < 512) ? 0 : 3;
        int coff = (b < 512) ? 32 : 0;
        int nb = (b < 512) ? 512 : 256;
        int bb = (b < 512) ? b : b - 512;
        int c = threadIdx.x & 31;
        int g = threadIdx.x >> 5;
        int gpb = blockDim.x >> 5;
        float s = 0.f, q = 0.f;
        for (int r = bb * gpb + g; r < rows; r += nb * gpb) {
            float v = src[(size_t)r * 32 + c];
            s += v; q += v * v;
        }
        atomicAdd(&g_sum[stage][coff + c], s);
        atomicAdd(&g_sq[stage][coff + c], q);
    } else {
        int i = (b - 768) * blockDim.x + threadIdx.x;
        int stride = 1024 * blockDim.x;
        for (int e = i; e < E; e += stride) atomicAdd(&g_deg[row[e]], 1);
    }
}

// ---------------- degree-weighted x stats -> stats0 cols [0,32) ----------------
__global__ void k_degw(const float* __restrict__ x, int n) {
    int c = threadIdx.x & 31;
    int g = threadIdx.x >> 5;
    int gpb = blockDim.x >> 5;
    float s = 0.f, q = 0.f;
    for (int r = blockIdx.x * gpb + g; r < n; r += gridDim.x * gpb) {
        float w = (float)g_deg[r];
        float v = x[(size_t)r * 32 + c];
        float wv = w * v;
        s += wv; q += wv * v;
    }
    atomicAdd(&g_sum[0][c], s);
    atomicAdd(&g_sq[0][c], q);
}

// ---------------- generic column stats (sum, sumsq) ----------------
template <int C>
__global__ void k_colstats(const float* __restrict__ src, int rows, int stage, int coff) {
    int gpb = blockDim.x / C;
    int c = threadIdx.x % C;
    int g = threadIdx.x / C;
    if (g >= gpb) return;
    float s = 0.f, q = 0.f;
    for (int r = blockIdx.x * gpb + g; r < rows; r += gridDim.x * gpb) {
        float v = src[(size_t)r * C + c];
        s += v; q += v * v;
    }
    atomicAdd(&g_sum[stage][coff + c], s);
    atomicAdd(&g_sq[stage][coff + c], q);
}

// ---------------- fold BN stats into weights: Wf = scale*W, cf = c + shift@W ----------------
__global__ void k_prep(int stage, float invR,
                       const float* __restrict__ gg, const float* __restrict__ bb,
                       const float* __restrict__ W, const float* __restrict__ c,
                       int IN, int OUT) {
    __shared__ float sSc[96], sSh[96];
    int t = threadIdx.x;
    if (t < IN) {
        float m = g_sum[stage][t] * invR;
        float var = g_sq[stage][t] * invR - m * m;
        float sc = gg[t] * rsqrtf(var + EPS_);
        sSc[t] = sc;
        sSh[t] = bb[t] - m * sc;
    }
    __syncthreads();
    for (int j = t; j < OUT; j += blockDim.x) {
        float a = c[j];
        for (int k = 0; k < IN; k++) {
            float w = W[k * OUT + j];
            g_Wf[stage][k * OUT + j] = sSc[k] * w;
            a += sSh[k] * w;
        }
        g_cf[stage][j] = a;
    }
}

// ---------------- staging helper: copy rows into padded smem (stride mult of 4) ----------------
template <int W>
__device__ __forceinline__ void stage_copy(const float* __restrict__ src, int base, int rows,
                                           float* sIn, int stride, int coff) {
    const int total = 128 * (W / 4);
    for (int idx = threadIdx.x; idx < total; idx += blockDim.x) {
        int r = idx / (W / 4);
        int kk = (idx % (W / 4)) * 4;
        if (base + r < rows) {
            float4 v = *(const float4*)(src + (size_t)(base + r) * W + kk);
            *(float4*)(sIn + r * stride + coff + kk) = v;
        }
    }
}

// ---------------- per-row GEMM core, explicit float4 LDS: acc = cf + in @ Wf ----------------
// sIn must be 16B-aligned (row stride multiple of 4 floats)
template <int IN, int OUT, bool LRELU>
__device__ __forceinline__ void gemm_one(const float* __restrict__ sIn, const float* __restrict__ sW,
                                         const float* __restrict__ cf, float* acc) {
#pragma unroll
    for (int j = 0; j < OUT / 4; j++) {
        float4 c4 = __ldg((const float4*)cf + j);
        acc[4 * j] = c4.x; acc[4 * j + 1] = c4.y; acc[4 * j + 2] = c4.z; acc[4 * j + 3] = c4.w;
    }
#pragma unroll 1
    for (int k = 0; k < IN; k += 4) {
        float4 a4 = *(const float4*)(sIn + k);
#pragma unroll
        for (int kk = 0; kk < 4; kk++) {
            float v = (kk == 0) ? a4.x : (kk == 1) ? a4.y : (kk == 2) ? a4.z : a4.w;
            const float4* w4 = (const float4*)(sW + (k + kk) * OUT);
#pragma unroll
            for (int j = 0; j < OUT / 4; j++) {
                float4 w = w4[j];
                acc[4 * j]     = fmaf(v, w.x, acc[4 * j]);
                acc[4 * j + 1] = fmaf(v, w.y, acc[4 * j + 1]);
                acc[4 * j + 2] = fmaf(v, w.z, acc[4 * j + 2]);
                acc[4 * j + 3] = fmaf(v, w.w, acc[4 * j + 3]);
            }
        }
    }
    if (LRELU) {
#pragma unroll
        for (int j = 0; j < OUT; j++) acc[j] = acc[j] > 0.f ? acc[j] : SLOPE_ * acc[j];
    }
}

// ---------------- fused in-block column stats over smem tile ----------------
template <int C>
__device__ __forceinline__ void block_stats(const float* __restrict__ sOut, int stride,
                                            int nvalid, int ostage) {
    int t = threadIdx.x;
    if (C == 64) {
        int c = t & 63;
        int half = t >> 6;
        int r0 = half * 64;
        int r1 = min(nvalid, r0 + 64);
        float s = 0.f, q = 0.f;
        for (int r = r0; r < r1; r++) {
            float v = sOut[r * stride + c];
            s += v; q += v * v;
        }
        if (r1 > r0) {
            atomicAdd(&g_sum[ostage][c], s);
            atomicAdd(&g_sq[ostage][c], q);
        }
    } else {
        if (t < C) {
            float s = 0.f, q = 0.f;
            for (int r = 0; r < nvalid; r++) {
                float v = sOut[r * stride + t];
                s += v; q += v * v;
            }
            atomicAdd(&g_sum[ostage][t], s);
            atomicAdd(&g_sq[ostage][t], q);
        }
    }
}

// ---------------- layer 1 of edge MLP: gather x[row] || edge_attr, 64->64, LReLU, +stats ----------------
__global__ __launch_bounds__(128) void k_edge1(const float* __restrict__ x, const int* __restrict__ row,
                                               const float* __restrict__ ea, float* __restrict__ dst,
                                               int E, int stage, int ostage) {
    extern __shared__ float sm[];
    float* sW = sm;              // 64*64
    float* sIn = sm + 64 * 64;   // 128*68
    for (int i = threadIdx.x; i < 64 * 64 / 4; i += 128)
        ((float4*)sW)[i] = ((const float4*)g_Wf[stage])[i];
    int base = blockIdx.x * 128;
    stage_copy<32>(ea, base, E, sIn, 68, 32);
    int e = base + threadIdx.x;
    if (e < E) {
        int rn = row[e];
        const float4* xr = (const float4*)(x + (size_t)rn * 32);
        float4* d = (float4*)(sIn + threadIdx.x * 68);
#pragma unroll
        for (int k = 0; k < 8; k++) d[k] = xr[k];
    }
    __syncthreads();
    float acc[64];
    if (e < E) {
        gemm_one<64, 64, true>(sIn + threadIdx.x * 68, sW, g_cf[stage], acc);
        float4* d = (float4*)(dst + (size_t)e * 64);
#pragma unroll
        for (int j = 0; j < 16; j++)
            d[j] = make_float4(acc[4 * j], acc[4 * j + 1], acc[4 * j + 2], acc[4 * j + 3]);
        float4* so = (float4*)(sIn + threadIdx.x * 68);  // own row only: no cross-thread hazard
#pragma unroll
        for (int j = 0; j < 16; j++)
            so[j] = make_float4(acc[4 * j], acc[4 * j + 1], acc[4 * j + 2], acc[4 * j + 3]);
    }
    __syncthreads();
    block_stats<64>(sIn, 68, min(128, E - base), ostage);
}

// ---------------- generic dense layer, optional fused stats ----------------
template <int IN, int OUT, bool LRELU, bool STATS>
__global__ __launch_bounds__(128) void k_layer(const float* __restrict__ src, float* __restrict__ dst,
                                               int rows, int stage, int ostage) {
    constexpr int LD = IN + 4;
    extern __shared__ float sm[];
    float* sW = sm;               // IN*OUT
    float* sIn = sm + IN * OUT;   // 128*LD
    for (int i = threadIdx.x; i < IN * OUT / 4; i += 128)
        ((float4*)sW)[i] = ((const float4*)g_Wf[stage])[i];
    int base = blockIdx.x * 128;
    stage_copy<IN>(src, base, rows, sIn, LD, 0);
    __syncthreads();
    int r = base + threadIdx.x;
    float acc[OUT];
    if (r < rows) {
        gemm_one<IN, OUT, LRELU>(sIn + threadIdx.x * LD, sW, g_cf[stage], acc);
        float4* d = (float4*)(dst + (size_t)r * OUT);
#pragma unroll
        for (int j = 0; j < OUT / 4; j++)
            d[j] = make_float4(acc[4 * j], acc[4 * j + 1], acc[4 * j + 2], acc[4 * j + 3]);
        if (STATS) {
            float4* so = (float4*)(sIn + threadIdx.x * LD);
#pragma unroll
            for (int j = 0; j < OUT / 4; j++)
                so[j] = make_float4(acc[4 * j], acc[4 * j + 1], acc[4 * j + 2], acc[4 * j + 3]);
        }
    }
    if (STATS) {
        __syncthreads();
        block_stats<OUT>(sIn, LD, min(128, rows - base), ostage);
    }
}

// ---------------- edge MLP layer 3 + vectorized scatter-sum to g_agg ----------------
__global__ __launch_bounds__(128) void k_scatter(const float* __restrict__ src, const int* __restrict__ col,
                                                 int rows, int stage) {
    extern __shared__ float sm[];
    float* sW = sm;
    float* sIn = sm + 64 * 64;
    for (int i = threadIdx.x; i < 64 * 64 / 4; i += 128)
        ((float4*)sW)[i] = ((const float4*)g_Wf[stage])[i];
    int base = blockIdx.x * 128;
    stage_copy<64>(src, base, rows, sIn, 68, 0);
    __syncthreads();
    int e = base + threadIdx.x;
    if (e >= rows) return;
    float acc[64];
    gemm_one<64, 64, false>(sIn + threadIdx.x * 68, sW, g_cf[stage], acc);
    float* d = g_agg + (size_t)col[e] * 64;
#pragma unroll
    for (int j = 0; j < 64; j += 4) {
        asm volatile("red.global.add.v4.f32 [%0], {%1, %2, %3, %4};"
                     :: "l"(d + j), "f"(acc[j]), "f"(acc[j + 1]), "f"(acc[j + 2]), "f"(acc[j + 3])
                     : "memory");
    }
}

// ---------------- node MLP layer 1: concat(x, agg) -> 96, LReLU, +stats ----------------
__global__ __launch_bounds__(128) void k_node1(const float* __restrict__ x, float* __restrict__ dst,
                                               int n, int stage, int ostage) {
    extern __shared__ float sm[];
    float* sW = sm;               // 96*96
    float* sIn = sm + 96 * 96;    // 128*100
    for (int i = threadIdx.x; i < 96 * 96 / 4; i += 128)
        ((float4*)sW)[i] = ((const float4*)g_Wf[stage])[i];
    int base = blockIdx.x * 128;
    stage_copy<32>(x, base, n, sIn, 100, 0);
    stage_copy<64>(g_agg, base, n, sIn, 100, 32);
    __syncthreads();
    int r = base + threadIdx.x;
    float acc[96];
    if (r < n) {
        gemm_one<96, 96, true>(sIn + threadIdx.x * 100, sW, g_cf[stage], acc);
        float4* d = (float4*)(dst + (size_t)r * 96);
#pragma unroll
        for (int j = 0; j < 24; j++)
            d[j] = make_float4(acc[4 * j], acc[4 * j + 1], acc[4 * j + 2], acc[4 * j + 3]);
        float4* so = (float4*)(sIn + threadIdx.x * 100);
#pragma unroll
        for (int j = 0; j < 24; j++)
            so[j] = make_float4(acc[4 * j], acc[4 * j + 1], acc[4 * j + 2], acc[4 * j + 3]);
    }
    __syncthreads();
    block_stats<96>(sIn, 100, min(128, n - base), ostage);
}

// ---------------- launcher ----------------
extern "C" void kernel_launch(void* const* d_in, const int* in_sizes, int n_in,
                              void* d_out, int out_size) {
    (void)n_in; (void)out_size;
    const float* x  = (const float*)d_in[0];
    const int*   ei = (const int*)d_in[1];
    const float* ea = (const float*)d_in[2];
    const float* m1g1 = (const float*)d_in[5],  *m1b1 = (const float*)d_in[6];
    const float* m1w1 = (const float*)d_in[7],  *m1c1 = (const float*)d_in[8];
    const float* m1g2 = (const float*)d_in[9],  *m1b2 = (const float*)d_in[10];
    const float* m1w2 = (const float*)d_in[11], *m1c2 = (const float*)d_in[12];
    const float* m1g3 = (const float*)d_in[13], *m1b3 = (const float*)d_in[14];
    const float* m1w3 = (const float*)d_in[15], *m1c3 = (const float*)d_in[16];
    const float* m2g1 = (const float*)d_in[17], *m2b1 = (const float*)d_in[18];
    const float* m2w1 = (const float*)d_in[19], *m2c1 = (const float*)d_in[20];
    const float* m2g2 = (const float*)d_in[21], *m2b2 = (const float*)d_in[22];
    const float* m2w2 = (const float*)d_in[23], *m2c2 = (const float*)d_in[24];
    const float* m2g3 = (const float*)d_in[25], *m2b3 = (const float*)d_in[26];
    const float* m2w3 = (const float*)d_in[27], *m2c3 = (const float*)d_in[28];

    int N = in_sizes[0] / 32;
    int E = in_sizes[2] / 32;
    const int* rowp = ei;
    const int* colp = ei + E;

    float *hA, *hB, *aggp, *h2A, *h2B;
    int* degp;
    float *sump, *sqp;
    cudaGetSymbolAddress((void**)&hA, g_hA);
    cudaGetSymbolAddress((void**)&hB, g_hB);
    cudaGetSymbolAddress((void**)&aggp, g_agg);
    cudaGetSymbolAddress((void**)&h2A, g_h2A);
    cudaGetSymbolAddress((void**)&h2B, g_h2B);
    cudaGetSymbolAddress((void**)&degp, g_deg);
    cudaGetSymbolAddress((void**)&sump, g_sum);
    cudaGetSymbolAddress((void**)&sqp, g_sq);

    const int SM64    = (64 * 64 + 128 * 68) * 4;    // 51200 B
    const int SM96    = (96 * 96 + 128 * 100) * 4;   // 88064 B
    const int SM96_32 = (96 * 32 + 128 * 100) * 4;   // 63488 B
    cudaFuncSetAttribute(k_edge1, cudaFuncAttributeMaxDynamicSharedMemorySize, SM64);
    cudaFuncSetAttribute(k_layer<64, 64, true, true>, cudaFuncAttributeMaxDynamicSharedMemorySize, SM64);
    cudaFuncSetAttribute(k_scatter, cudaFuncAttributeMaxDynamicSharedMemorySize, SM64);
    cudaFuncSetAttribute(k_node1, cudaFuncAttributeMaxDynamicSharedMemorySize, SM96);
    cudaFuncSetAttribute(k_layer<96, 96, true, true>, cudaFuncAttributeMaxDynamicSharedMemorySize, SM96);
    cudaFuncSetAttribute(k_layer<96, 32, false, false>, cudaFuncAttributeMaxDynamicSharedMemorySize, SM96_32);

    int ebl = (E + 127) / 128;
    int nbl = (N + 127) / 128;

    // zeroing via memsets (not kernel launches -> keeps k_edge1 in ncu's profiled slot)
    cudaMemsetAsync(aggp, 0, (size_t)N * 64 * sizeof(float), 0);
    cudaMemsetAsync(degp, 0, (size_t)N * sizeof(int), 0);
    cudaMemsetAsync(sump, 0, 6 * 96 * sizeof(float), 0);
    cudaMemsetAsync(sqp, 0, 6 * 96 * sizeof(float), 0);

    // [0] merged: ea stats (stage0 cols 32-63) + x stats (stage3 cols 0-31) + degree count
    k_edgestats<<<1792, 256>>>(ea, x, rowp, E, N);
    // [1] degree-weighted x stats -> stage0 cols 0-31
    k_degw<<<1024, 256>>>(x, N);
    // [2] fold stage 0
    k_prep<<<1, 128>>>(0, 1.0f / E, m1g1, m1b1, m1w1, m1c1, 64, 64);
    // [3] edge layer 1 (gather + GEMM + lrelu + fused stats->1)  <- ncu profiled slot
    k_edge1<<<ebl, 128, SM64>>>(x, rowp, ea, hA, E, 0, 1);

    k_prep<<<1, 128>>>(1, 1.0f / E, m1g2, m1b2, m1w2, m1c2, 64, 64);
    k_layer<64, 64, true, true><<<ebl, 128, SM64>>>(hA, hB, E, 1, 2);

    k_prep<<<1, 128>>>(2, 1.0f / E, m1g3, m1b3, m1w3, m1c3, 64, 64);
    k_scatter<<<ebl, 128, SM64>>>(hB, colp, E, 2);

    // agg stats -> stage3 cols 32-95
    k_colstats<64><<<256, 256>>>(aggp, N, 3, 32);
    k_prep<<<1, 128>>>(3, 1.0f / N, m2g1, m2b1, m2w1, m2c1, 96, 96);
    k_node1<<<nbl, 128, SM96>>>(x, h2A, N, 3, 4);

    k_prep<<<1, 128>>>(4, 1.0f / N, m2g2, m2b2, m2w2, m2c2, 96, 96);
    k_layer<96, 96, true, true><<<nbl, 128, SM96>>>(h2A, h2B, N, 4, 5);

    k_prep<<<1, 128>>>(5, 1.0f / N, m2g3, m2b3, m2w3, m2c3, 96, 32);
    k_layer<96, 32, false, false><<<nbl, 128, SM96_32>>>(h2B, (float*)d_out, N, 5, 0);
}

// round 17
// speedup vs baseline: 1.2047x; 1.2047x over previous
#include <cuda_runtime.h>

#define EMAX 800000
#define NMAX 100000
#define SLOPE_ 0.1f
#define EPS_ 1e-5f

// ---------------- scratch (device globals; no allocation allowed) ----------------
__device__ float g_hA[(size_t)EMAX * 64];   // edge intermediate A
__device__ float g_hB[(size_t)EMAX * 64];   // edge intermediate B
__device__ float g_agg[(size_t)NMAX * 64];  // scatter-sum result
__device__ float g_h2A[(size_t)NMAX * 96];
__device__ float g_h2B[(size_t)NMAX * 96];
__device__ int   g_deg[NMAX];
__device__ float g_sum[6][96];
__device__ float g_sq[6][96];
__device__ float g_Wf[6][96 * 96];          // folded (scale*W) per stage
__device__ __align__(16) float g_cf[6][96]; // folded bias per stage

// ---------------- merged prologue stats: ea col-stats + deg count + x col-stats ----------------
__global__ void k_edgestats(const float* __restrict__ ea, const float* __restrict__ x,
                            const int* __restrict__ row, int E, int N) {
    int b = blockIdx.x;
    if (b < 768) {
        const float* src = (b < 512) ? ea : x;
        int rows = (b < 512) ? E : N;
        int stage = (b < 512) ? 0 : 3;
        int coff = (b < 512) ? 32 : 0;
        int nb = (b < 512) ? 512 : 256;
        int bb = (b < 512) ? b : b - 512;
        int c = threadIdx.x & 31;
        int g = threadIdx.x >> 5;
        int gpb = blockDim.x >> 5;
        float s = 0.f, q = 0.f;
        for (int r = bb * gpb + g; r < rows; r += nb * gpb) {
            float v = src[(size_t)r * 32 + c];
            s += v; q += v * v;
        }
        atomicAdd(&g_sum[stage][coff + c], s);
        atomicAdd(&g_sq[stage][coff + c], q);
    } else {
        int i = (b - 768) * blockDim.x + threadIdx.x;
        int stride = 1024 * blockDim.x;
        for (int e = i; e < E; e += stride) atomicAdd(&g_deg[row[e]], 1);
    }
}

// ---------------- degree-weighted x stats -> stats0 cols [0,32) ----------------
__global__ void k_degw(const float* __restrict__ x, int n) {
    int c = threadIdx.x & 31;
    int g = threadIdx.x >> 5;
    int gpb = blockDim.x >> 5;
    float s = 0.f, q = 0.f;
    for (int r = blockIdx.x * gpb + g; r < n; r += gridDim.x * gpb) {
        float w = (float)g_deg[r];
        float v = x[(size_t)r * 32 + c];
        float wv = w * v;
        s += wv; q += wv * v;
    }
    atomicAdd(&g_sum[0][c], s);
    atomicAdd(&g_sq[0][c], q);
}

// ---------------- generic column stats (sum, sumsq) ----------------
template <int C>
__global__ void k_colstats(const float* __restrict__ src, int rows, int stage, int coff) {
    int gpb = blockDim.x / C;
    int c = threadIdx.x % C;
    int g = threadIdx.x / C;
    if (g >= gpb) return;
    float s = 0.f, q = 0.f;
    for (int r = blockIdx.x * gpb + g; r < rows; r += gridDim.x * gpb) {
        float v = src[(size_t)r * C + c];
        s += v; q += v * v;
    }
    atomicAdd(&g_sum[stage][coff + c], s);
    atomicAdd(&g_sq[stage][coff + c], q);
}

// ---------------- fold BN stats into weights: Wf = scale*W, cf = c + shift@W ----------------
__global__ void k_prep(int stage, float invR,
                       const float* __restrict__ gg, const float* __restrict__ bb,
                       const float* __restrict__ W, const float* __restrict__ c,
                       int IN, int OUT) {
    __shared__ float sSc[96], sSh[96];
    int t = threadIdx.x;
    if (t < IN) {
        float m = g_sum[stage][t] * invR;
        float var = g_sq[stage][t] * invR - m * m;
        float sc = gg[t] * rsqrtf(var + EPS_);
        sSc[t] = sc;
        sSh[t] = bb[t] - m * sc;
    }
    __syncthreads();
    for (int j = t; j < OUT; j += blockDim.x) {
        float a = c[j];
        for (int k = 0; k < IN; k++) {
            float w = W[k * OUT + j];
            g_Wf[stage][k * OUT + j] = sSc[k] * w;
            a += sSh[k] * w;
        }
        g_cf[stage][j] = a;
    }
}

// ---------------- staging helper: copy 128 rows of width W into smem (scalar stores) ----------------
template <int W>
__device__ __forceinline__ void stage_copy(const float* __restrict__ src, int base, int rows,
                                           float* sIn, int stride, int coff) {
    const int total = 128 * (W / 4);
    for (int idx = threadIdx.x; idx < total; idx += blockDim.x) {
        int r = idx / (W / 4);
        int kk = (idx % (W / 4)) * 4;
        if (base + r < rows) {
            float4 v = *(const float4*)(src + (size_t)(base + r) * W + kk);
            float* d = sIn + r * stride + coff + kk;
            d[0] = v.x; d[1] = v.y; d[2] = v.z; d[3] = v.w;
        }
    }
}

// ---------------- fused in-block column stats over smem tile (R4-proven) ----------------
template <int C>
__device__ __forceinline__ void block_stats(const float* __restrict__ sOut, int stride,
                                            int nvalid, int ostage) {
    int t = threadIdx.x;
    if (C == 64) {
        int c = t & 63;
        int half = t >> 6;
        int r0 = half * 64;
        int r1 = min(nvalid, r0 + 64);
        float s = 0.f, q = 0.f;
        for (int r = r0; r < r1; r++) {
            float v = sOut[r * stride + c];
            s += v; q += v * v;
        }
        if (r1 > r0) {
            atomicAdd(&g_sum[ostage][c], s);
            atomicAdd(&g_sq[ostage][c], q);
        }
    } else {
        if (t < C) {
            float s = 0.f, q = 0.f;
            for (int r = 0; r < nvalid; r++) {
                float v = sOut[r * stride + t];
                s += v; q += v * v;
            }
            atomicAdd(&g_sum[ostage][t], s);
            atomicAdd(&g_sq[ostage][t], q);
        }
    }
}

// ================ row-blocked GEMM layer: R=4 rows x C=16 cols per thread ================
// CTA tile: 128 rows x OUT cols. Warp w owns cols [16w,16w+16); lane l owns rows {l,l+32,l+64,l+96}.
// Weight LDS is warp-uniform (4x LDS.128 per k) -> weight bytes per CTA cut 4x vs thread-per-row.
// MODE: 0 = plain src[IN]; 1 = gather x[rowp[e]](32) || src(32); 2 = x[r](32) || src[r](64)
template <int IN, int OUT, int MODE, bool LRELU, bool STATS, bool SCATTER>
__global__ __launch_bounds__((OUT / 16) * 32) void k_blk(
    const float* __restrict__ src, const float* __restrict__ x,
    const int* __restrict__ rowp, const int* __restrict__ colp,
    float* __restrict__ dst, int rows, int stage, int ostage) {
    constexpr int T = (OUT / 16) * 32;
    constexpr int LD = IN + 1;   // odd stride: row-step-32 scalar A loads are bank-conflict-free
    extern __shared__ float sm[];
    float* sW = sm;              // [IN][OUT]
    float* sCF = sm + IN * OUT;  // [OUT]
    float* sIn = sCF + OUT;      // [128][LD]
    int tid = threadIdx.x;
    int base = blockIdx.x * 128;

    for (int i = tid; i < IN * OUT / 4; i += T)
        ((float4*)sW)[i] = ((const float4*)g_Wf[stage])[i];
    if (tid < OUT) sCF[tid] = g_cf[stage][tid];

    if (MODE == 0) {
        stage_copy<IN>(src, base, rows, sIn, LD, 0);
    } else if (MODE == 1) {  // T == 128 here
        stage_copy<32>(src, base, rows, sIn, LD, 32);   // edge_attr -> cols [32,64)
        int e = base + tid;
        if (e < rows) {
            int rn = rowp[e];
            const float4* xr = (const float4*)(x + (size_t)rn * 32);
            float* d = sIn + tid * LD;
#pragma unroll
            for (int k = 0; k < 8; k++) {
                float4 v = xr[k];
                d[4 * k] = v.x; d[4 * k + 1] = v.y; d[4 * k + 2] = v.z; d[4 * k + 3] = v.w;
            }
        }
    } else {
        stage_copy<32>(x, base, rows, sIn, LD, 0);      // x -> cols [0,32)
        stage_copy<64>(src, base, rows, sIn, LD, 32);   // agg -> cols [32,96)
    }
    __syncthreads();

    int w = tid >> 5, l = tid & 31;
    float acc[4][16];
#pragma unroll
    for (int j = 0; j < 16; j++) {
        float c = sCF[w * 16 + j];
        acc[0][j] = c; acc[1][j] = c; acc[2][j] = c; acc[3][j] = c;
    }
    const float* pw = sW + w * 16;
    const float* pa = sIn + l * LD;
#pragma unroll 1
    for (int k = 0; k < IN; k++) {
        float a0 = pa[k];
        float a1 = pa[32 * LD + k];
        float a2 = pa[64 * LD + k];
        float a3 = pa[96 * LD + k];
        const float4* wrow = (const float4*)(pw + k * OUT);
#pragma unroll
        for (int jj = 0; jj < 4; jj++) {
            float4 w4 = wrow[jj];
            acc[0][4 * jj]     = fmaf(a0, w4.x, acc[0][4 * jj]);
            acc[0][4 * jj + 1] = fmaf(a0, w4.y, acc[0][4 * jj + 1]);
            acc[0][4 * jj + 2] = fmaf(a0, w4.z, acc[0][4 * jj + 2]);
            acc[0][4 * jj + 3] = fmaf(a0, w4.w, acc[0][4 * jj + 3]);
            acc[1][4 * jj]     = fmaf(a1, w4.x, acc[1][4 * jj]);
            acc[1][4 * jj + 1] = fmaf(a1, w4.y, acc[1][4 * jj + 1]);
            acc[1][4 * jj + 2] = fmaf(a1, w4.z, acc[1][4 * jj + 2]);
            acc[1][4 * jj + 3] = fmaf(a1, w4.w, acc[1][4 * jj + 3]);
            acc[2][4 * jj]     = fmaf(a2, w4.x, acc[2][4 * jj]);
            acc[2][4 * jj + 1] = fmaf(a2, w4.y, acc[2][4 * jj + 1]);
            acc[2][4 * jj + 2] = fmaf(a2, w4.z, acc[2][4 * jj + 2]);
            acc[2][4 * jj + 3] = fmaf(a2, w4.w, acc[2][4 * jj + 3]);
            acc[3][4 * jj]     = fmaf(a3, w4.x, acc[3][4 * jj]);
            acc[3][4 * jj + 1] = fmaf(a3, w4.y, acc[3][4 * jj + 1]);
            acc[3][4 * jj + 2] = fmaf(a3, w4.z, acc[3][4 * jj + 2]);
            acc[3][4 * jj + 3] = fmaf(a3, w4.w, acc[3][4 * jj + 3]);
        }
    }
    if (LRELU) {
#pragma unroll
        for (int i = 0; i < 4; i++)
#pragma unroll
            for (int j = 0; j < 16; j++)
                acc[i][j] = acc[i][j] > 0.f ? acc[i][j] : SLOPE_ * acc[i][j];
    }

    __syncthreads();   // all warps done reading sIn -> safe to overwrite with outputs
#pragma unroll
    for (int i = 0; i < 4; i++) {
        float* so = sIn + (l + 32 * i) * LD + w * 16;
#pragma unroll
        for (int j = 0; j < 16; j++) so[j] = acc[i][j];
    }
    __syncthreads();

    // output phase: row-major from smem (coalesced-per-thread), plus fused stats
    for (int rr = tid; rr < 128; rr += T) {
        int r = base + rr;
        if (r >= rows) break;
        const float* so = sIn + rr * LD;
        if (SCATTER) {
            float* d = g_agg + (size_t)colp[r] * 64;
#pragma unroll
            for (int j = 0; j < OUT; j += 4) {
                asm volatile("red.global.add.v4.f32 [%0], {%1, %2, %3, %4};"
                             :: "l"(d + j), "f"(so[j]), "f"(so[j + 1]), "f"(so[j + 2]), "f"(so[j + 3])
                             : "memory");
            }
        } else {
            float4* d = (float4*)(dst + (size_t)r * OUT);
#pragma unroll
            for (int j = 0; j < OUT / 4; j++)
                d[j] = make_float4(so[4 * j], so[4 * j + 1], so[4 * j + 2], so[4 * j + 3]);
        }
    }
    if (STATS) block_stats<OUT>(sIn, LD, min(128, rows - base), ostage);
}

// ---------------- launcher ----------------
extern "C" void kernel_launch(void* const* d_in, const int* in_sizes, int n_in,
                              void* d_out, int out_size) {
    (void)n_in; (void)out_size;
    const float* x  = (const float*)d_in[0];
    const int*   ei = (const int*)d_in[1];
    const float* ea = (const float*)d_in[2];
    const float* m1g1 = (const float*)d_in[5],  *m1b1 = (const float*)d_in[6];
    const float* m1w1 = (const float*)d_in[7],  *m1c1 = (const float*)d_in[8];
    const float* m1g2 = (const float*)d_in[9],  *m1b2 = (const float*)d_in[10];
    const float* m1w2 = (const float*)d_in[11], *m1c2 = (const float*)d_in[12];
    const float* m1g3 = (const float*)d_in[13], *m1b3 = (const float*)d_in[14];
    const float* m1w3 = (const float*)d_in[15], *m1c3 = (const float*)d_in[16];
    const float* m2g1 = (const float*)d_in[17], *m2b1 = (const float*)d_in[18];
    const float* m2w1 = (const float*)d_in[19], *m2c1 = (const float*)d_in[20];
    const float* m2g2 = (const float*)d_in[21], *m2b2 = (const float*)d_in[22];
    const float* m2w2 = (const float*)d_in[23], *m2c2 = (const float*)d_in[24];
    const float* m2g3 = (const float*)d_in[25], *m2b3 = (const float*)d_in[26];
    const float* m2w3 = (const float*)d_in[27], *m2c3 = (const float*)d_in[28];

    int N = in_sizes[0] / 32;
    int E = in_sizes[2] / 32;
    const int* rowp = ei;
    const int* colp = ei + E;

    float *hA, *hB, *aggp, *h2A, *h2B;
    int* degp;
    float *sump, *sqp;
    cudaGetSymbolAddress((void**)&hA, g_hA);
    cudaGetSymbolAddress((void**)&hB, g_hB);
    cudaGetSymbolAddress((void**)&aggp, g_agg);
    cudaGetSymbolAddress((void**)&h2A, g_h2A);
    cudaGetSymbolAddress((void**)&h2B, g_h2B);
    cudaGetSymbolAddress((void**)&degp, g_deg);
    cudaGetSymbolAddress((void**)&sump, g_sum);
    cudaGetSymbolAddress((void**)&sqp, g_sq);

    const int SM_E = (64 * 64 + 64 + 128 * 65) * 4;   // 49920 B
    const int SM_N = (96 * 96 + 96 + 128 * 97) * 4;   // 86912 B
    const int SM_F = (96 * 32 + 32 + 128 * 97) * 4;   // 62080 B
    cudaFuncSetAttribute(k_blk<64, 64, 1, true, true, false>, cudaFuncAttributeMaxDynamicSharedMemorySize, SM_E);
    cudaFuncSetAttribute(k_blk<64, 64, 0, true, true, false>, cudaFuncAttributeMaxDynamicSharedMemorySize, SM_E);
    cudaFuncSetAttribute(k_blk<64, 64, 0, false, false, true>, cudaFuncAttributeMaxDynamicSharedMemorySize, SM_E);
    cudaFuncSetAttribute(k_blk<96, 96, 2, true, true, false>, cudaFuncAttributeMaxDynamicSharedMemorySize, SM_N);
    cudaFuncSetAttribute(k_blk<96, 96, 0, true, true, false>, cudaFuncAttributeMaxDynamicSharedMemorySize, SM_N);
    cudaFuncSetAttribute(k_blk<96, 32, 0, false, false, false>, cudaFuncAttributeMaxDynamicSharedMemorySize, SM_F);

    int ebl = (E + 127) / 128;
    int nbl = (N + 127) / 128;

    // zeroing via memsets (not kernel launches -> keeps the edge GEMM in ncu's profiled slot)
    cudaMemsetAsync(aggp, 0, (size_t)N * 64 * sizeof(float), 0);
    cudaMemsetAsync(degp, 0, (size_t)N * sizeof(int), 0);
    cudaMemsetAsync(sump, 0, 6 * 96 * sizeof(float), 0);
    cudaMemsetAsync(sqp, 0, 6 * 96 * sizeof(float), 0);

    // [0] merged: ea stats (stage0 cols 32-63) + x stats (stage3 cols 0-31) + degree count
    k_edgestats<<<1792, 256>>>(ea, x, rowp, E, N);
    // [1] degree-weighted x stats -> stage0 cols 0-31
    k_degw<<<1024, 256>>>(x, N);
    // [2] fold stage 0
    k_prep<<<1, 128>>>(0, 1.0f / E, m1g1, m1b1, m1w1, m1c1, 64, 64);
    // [3] edge layer 1 (gather + GEMM + lrelu + fused stats->1)  <- ncu profiled slot
    k_blk<64, 64, 1, true, true, false><<<ebl, 128, SM_E>>>(ea, x, rowp, nullptr, hA, E, 0, 1);

    k_prep<<<1, 128>>>(1, 1.0f / E, m1g2, m1b2, m1w2, m1c2, 64, 64);
    k_blk<64, 64, 0, true, true, false><<<ebl, 128, SM_E>>>(hA, nullptr, nullptr, nullptr, hB, E, 1, 2);

    k_prep<<<1, 128>>>(2, 1.0f / E, m1g3, m1b3, m1w3, m1c3, 64, 64);
    // edge layer 3 + scatter-sum
    k_blk<64, 64, 0, false, false, true><<<ebl, 128, SM_E>>>(hB, nullptr, nullptr, colp, nullptr, E, 2, 0);

    // agg stats -> stage3 cols 32-95
    k_colstats<64><<<256, 256>>>(aggp, N, 3, 32);
    k_prep<<<1, 128>>>(3, 1.0f / N, m2g1, m2b1, m2w1, m2c1, 96, 96);
    // node layer 1: concat(x, agg) + fused stats->4
    k_blk<96, 96, 2, true, true, false><<<nbl, 192, SM_N>>>(aggp, x, nullptr, nullptr, h2A, N, 3, 4);

    k_prep<<<1, 128>>>(4, 1.0f / N, m2g2, m2b2, m2w2, m2c2, 96, 96);
    k_blk<96, 96, 0, true, true, false><<<nbl, 192, SM_N>>>(h2A, nullptr, nullptr, nullptr, h2B, N, 4, 5);

    k_prep<<<1, 128>>>(5, 1.0f / N, m2g3, m2b3, m2w3, m2c3, 96, 32);
    k_blk<96, 32, 0, false, false, false><<<nbl, 64, SM_F>>>(h2B, nullptr, nullptr, nullptr, (float*)d_out, N, 5, 0);
}